// round 3
// baseline (speedup 1.0000x reference)
#include <cuda_runtime.h>

#define N_NODES   50000
#define N_EDGES   800000
#define F_IN      16
#define F_EDGE    8
#define H         8
#define NUM_GRAPHS 512
// Q row (o-major): 64 floats Q[o*8+f] + 8 floats of bias term (x@Be)
#define QSTRIDE   72

__device__ __align__(16) float g_Q[N_NODES * QSTRIDE];     // 14.4 MB
__device__ __align__(16) float g_agg1[N_NODES * H];        // 1.6 MB
__device__ __align__(16) float g_agg2[N_NODES * H];        // 1.6 MB

// ---------------------------------------------------------------------------
// Layer-1 node precompute (8 lanes per node, lane j = output channel j):
//   Q[n][j*8+f] = sum_i x[n,i]*We1[f, i*8+j]     (o-major)
//   Q[n][64+j]  = sum_i x[n,i]*be1[i*8+j]
//   agg1[n][j]  = x[n]@root1[:,j] + b1[j]
// ---------------------------------------------------------------------------
__global__ void node1_kernel(const float* __restrict__ x,
                             const float* __restrict__ We1,
                             const float* __restrict__ be1,
                             const float* __restrict__ root1,
                             const float* __restrict__ b1) {
    __shared__ float sW[F_EDGE * F_IN * H];  // 1024
    __shared__ float sR[F_IN * H];           // 128
    __shared__ float sB[F_IN * H];           // 128
    __shared__ float sb[H];
    for (int i = threadIdx.x; i < F_EDGE * F_IN * H; i += blockDim.x) sW[i] = We1[i];
    for (int i = threadIdx.x; i < F_IN * H; i += blockDim.x) { sR[i] = root1[i]; sB[i] = be1[i]; }
    if (threadIdx.x < H) sb[threadIdx.x] = b1[threadIdx.x];
    __syncthreads();

    int gid = blockIdx.x * blockDim.x + threadIdx.x;
    int n = gid >> 3, j = gid & 7;
    if (n >= N_NODES) return;

    float xv[F_IN];
    const float4* xp = (const float4*)(x + n * F_IN);
    #pragma unroll
    for (int v = 0; v < 4; v++) {
        float4 t = xp[v];
        xv[v * 4 + 0] = t.x; xv[v * 4 + 1] = t.y; xv[v * 4 + 2] = t.z; xv[v * 4 + 3] = t.w;
    }

    float q[8];
    #pragma unroll
    for (int f = 0; f < 8; f++) {
        float s = 0.f;
        #pragma unroll
        for (int i = 0; i < F_IN; i++) s = fmaf(xv[i], sW[f * 128 + i * 8 + j], s);
        q[f] = s;
    }
    float4* qp = (float4*)(g_Q + n * QSTRIDE + j * 8);
    qp[0] = make_float4(q[0], q[1], q[2], q[3]);
    qp[1] = make_float4(q[4], q[5], q[6], q[7]);

    float qb = 0.f, r = sb[j];
    #pragma unroll
    for (int i = 0; i < F_IN; i++) {
        qb = fmaf(xv[i], sB[i * 8 + j], qb);
        r  = fmaf(xv[i], sR[i * 8 + j], r);
    }
    g_Q[n * QSTRIDE + 64 + j] = qb;
    g_agg1[n * 8 + j] = r;
}

// ---------------------------------------------------------------------------
// Layer-2 node precompute: h = relu(agg1); same structure (o-major Q)
// ---------------------------------------------------------------------------
__global__ void node2_kernel(const float* __restrict__ We2,
                             const float* __restrict__ be2,
                             const float* __restrict__ root2,
                             const float* __restrict__ b2) {
    __shared__ float sW[F_EDGE * H * H];  // 512
    __shared__ float sR[H * H];           // 64
    __shared__ float sB[H * H];           // 64
    __shared__ float sb[H];
    for (int i = threadIdx.x; i < F_EDGE * H * H; i += blockDim.x) sW[i] = We2[i];
    for (int i = threadIdx.x; i < H * H; i += blockDim.x) { sR[i] = root2[i]; sB[i] = be2[i]; }
    if (threadIdx.x < H) sb[threadIdx.x] = b2[threadIdx.x];
    __syncthreads();

    int gid = blockIdx.x * blockDim.x + threadIdx.x;
    int n = gid >> 3, j = gid & 7;
    if (n >= N_NODES) return;

    float h[H];
    const float4* hp = (const float4*)(g_agg1 + n * 8);
    float4 a0 = hp[0], a1 = hp[1];
    h[0] = fmaxf(a0.x, 0.f); h[1] = fmaxf(a0.y, 0.f);
    h[2] = fmaxf(a0.z, 0.f); h[3] = fmaxf(a0.w, 0.f);
    h[4] = fmaxf(a1.x, 0.f); h[5] = fmaxf(a1.y, 0.f);
    h[6] = fmaxf(a1.z, 0.f); h[7] = fmaxf(a1.w, 0.f);

    float q[8];
    #pragma unroll
    for (int f = 0; f < 8; f++) {
        float s = 0.f;
        #pragma unroll
        for (int i = 0; i < H; i++) s = fmaf(h[i], sW[f * 64 + i * 8 + j], s);
        q[f] = s;
    }
    float4* qp = (float4*)(g_Q + n * QSTRIDE + j * 8);
    qp[0] = make_float4(q[0], q[1], q[2], q[3]);
    qp[1] = make_float4(q[4], q[5], q[6], q[7]);

    float qb = 0.f, r = sb[j];
    #pragma unroll
    for (int i = 0; i < H; i++) {
        qb = fmaf(h[i], sB[i * 8 + j], qb);
        r  = fmaf(h[i], sR[i * 8 + j], r);
    }
    g_Q[n * QSTRIDE + 64 + j] = qb;
    g_agg2[n * 8 + j] = r;
}

// ---------------------------------------------------------------------------
// Edge pass: 2 lanes per edge. Lane h owns channels 4h..4h+3.
//   r[c] = Qbias[src][4h+c] + sum_f ea[e,f] * Q[src][(4h+c)*8+f]
//   one red.global.add.v4.f32 to agg[dst*8 + 4h]
// 8 independent LDG.128 for Q give MLP=8 per thread; atomic instr-lanes
// drop 4x vs scalar atomics.
// ---------------------------------------------------------------------------
__device__ __forceinline__ void red_add_v4(float* p, float r0, float r1, float r2, float r3) {
    asm volatile(
        "{ .reg .u64 pg; cvta.to.global.u64 pg, %0;\n\t"
        "  red.global.add.v4.f32 [pg], {%1, %2, %3, %4}; }"
        :: "l"(p), "f"(r0), "f"(r1), "f"(r2), "f"(r3) : "memory");
}

__global__ void __launch_bounds__(256) edge_kernel(const int* __restrict__ ei,
                                                   const float* __restrict__ ea,
                                                   int layer) {
    int gid = blockIdx.x * blockDim.x + threadIdx.x;
    int e = gid >> 1, h = gid & 1;     // grid is exact: 2*N_EDGES threads

    int s = __ldg(&ei[e]);
    int d = __ldg(&ei[N_EDGES + e]);

    const float4* eap = (const float4*)(ea + e * 8);
    float4 a0 = __ldg(eap);
    float4 a1 = __ldg(eap + 1);

    const float4* qp = (const float4*)(g_Q + s * QSTRIDE + h * 32);
    float4 q0 = __ldg(qp + 0);
    float4 q1 = __ldg(qp + 1);
    float4 q2 = __ldg(qp + 2);
    float4 q3 = __ldg(qp + 3);
    float4 q4 = __ldg(qp + 4);
    float4 q5 = __ldg(qp + 5);
    float4 q6 = __ldg(qp + 6);
    float4 q7 = __ldg(qp + 7);
    float4 qb = __ldg((const float4*)(g_Q + s * QSTRIDE + 64 + h * 4));

    float r0 = qb.x, r1 = qb.y, r2 = qb.z, r3 = qb.w;
    // channel 4h+0 uses q0,q1 ; +1 uses q2,q3 ; +2 uses q4,q5 ; +3 uses q6,q7
    r0 = fmaf(a0.x, q0.x, r0); r0 = fmaf(a0.y, q0.y, r0);
    r0 = fmaf(a0.z, q0.z, r0); r0 = fmaf(a0.w, q0.w, r0);
    r0 = fmaf(a1.x, q1.x, r0); r0 = fmaf(a1.y, q1.y, r0);
    r0 = fmaf(a1.z, q1.z, r0); r0 = fmaf(a1.w, q1.w, r0);

    r1 = fmaf(a0.x, q2.x, r1); r1 = fmaf(a0.y, q2.y, r1);
    r1 = fmaf(a0.z, q2.z, r1); r1 = fmaf(a0.w, q2.w, r1);
    r1 = fmaf(a1.x, q3.x, r1); r1 = fmaf(a1.y, q3.y, r1);
    r1 = fmaf(a1.z, q3.z, r1); r1 = fmaf(a1.w, q3.w, r1);

    r2 = fmaf(a0.x, q4.x, r2); r2 = fmaf(a0.y, q4.y, r2);
    r2 = fmaf(a0.z, q4.z, r2); r2 = fmaf(a0.w, q4.w, r2);
    r2 = fmaf(a1.x, q5.x, r2); r2 = fmaf(a1.y, q5.y, r2);
    r2 = fmaf(a1.z, q5.z, r2); r2 = fmaf(a1.w, q5.w, r2);

    r3 = fmaf(a0.x, q6.x, r3); r3 = fmaf(a0.y, q6.y, r3);
    r3 = fmaf(a0.z, q6.z, r3); r3 = fmaf(a0.w, q6.w, r3);
    r3 = fmaf(a1.x, q7.x, r3); r3 = fmaf(a1.y, q7.y, r3);
    r3 = fmaf(a1.z, q7.z, r3); r3 = fmaf(a1.w, q7.w, r3);

    float* agg = layer ? g_agg2 : g_agg1;
    red_add_v4(agg + d * 8 + h * 4, r0, r1, r2, r3);
}

// ---------------------------------------------------------------------------
// Output init + fused relu / pool / readout with warp-aggregated atomics.
// ---------------------------------------------------------------------------
__global__ void out_init_kernel(const float* __restrict__ blast, float* __restrict__ out) {
    int g = blockIdx.x * blockDim.x + threadIdx.x;
    if (g < NUM_GRAPHS) out[g] = blast[0];
}

__global__ void final_kernel(const int* __restrict__ batch,
                             const float* __restrict__ Wlast,
                             float* __restrict__ out) {
    int n = blockIdx.x * blockDim.x + threadIdx.x;
    bool valid = (n < N_NODES);
    int nc = valid ? n : (N_NODES - 1);

    const float4* ap = (const float4*)(g_agg2 + nc * 8);
    float4 a0 = ap[0], a1 = ap[1];
    float v = 0.f;
    v = fmaf(fmaxf(a0.x, 0.f), __ldg(&Wlast[0]), v);
    v = fmaf(fmaxf(a0.y, 0.f), __ldg(&Wlast[1]), v);
    v = fmaf(fmaxf(a0.z, 0.f), __ldg(&Wlast[2]), v);
    v = fmaf(fmaxf(a0.w, 0.f), __ldg(&Wlast[3]), v);
    v = fmaf(fmaxf(a1.x, 0.f), __ldg(&Wlast[4]), v);
    v = fmaf(fmaxf(a1.y, 0.f), __ldg(&Wlast[5]), v);
    v = fmaf(fmaxf(a1.z, 0.f), __ldg(&Wlast[6]), v);
    v = fmaf(fmaxf(a1.w, 0.f), __ldg(&Wlast[7]), v);
    if (!valid) v = 0.f;

    int b = __ldg(&batch[nc]);
    int b0 = __shfl_sync(0xffffffffu, b, 0);
    if (__all_sync(0xffffffffu, b == b0)) {
        #pragma unroll
        for (int off = 16; off >= 1; off >>= 1)
            v += __shfl_xor_sync(0xffffffffu, v, off, 32);
        if ((threadIdx.x & 31) == 0) atomicAdd(&out[b0], v);
    } else {
        if (valid) atomicAdd(&out[b], v);
    }
}

// ---------------------------------------------------------------------------
extern "C" void kernel_launch(void* const* d_in, const int* in_sizes, int n_in,
                              void* d_out, int out_size) {
    const float* x     = (const float*)d_in[0];
    const int*   ei    = (const int*)  d_in[1];
    const float* ea    = (const float*)d_in[2];
    const int*   batch = (const int*)  d_in[3];
    const float* We1   = (const float*)d_in[4];
    const float* be1   = (const float*)d_in[5];
    const float* root1 = (const float*)d_in[6];
    const float* b1    = (const float*)d_in[7];
    const float* We2   = (const float*)d_in[8];
    const float* be2   = (const float*)d_in[9];
    const float* root2 = (const float*)d_in[10];
    const float* b2    = (const float*)d_in[11];
    const float* Wlast = (const float*)d_in[12];
    const float* blast = (const float*)d_in[13];
    float* out = (float*)d_out;

    const int TPB = 256;
    int node_blocks = (N_NODES * 8 + TPB - 1) / TPB;
    int edge_blocks = (N_EDGES * 2) / TPB;          // 6250, exact
    int fin_blocks  = (N_NODES + TPB - 1) / TPB;

    node1_kernel<<<node_blocks, TPB>>>(x, We1, be1, root1, b1);
    edge_kernel<<<edge_blocks, TPB>>>(ei, ea, 0);
    node2_kernel<<<node_blocks, TPB>>>(We2, be2, root2, b2);
    edge_kernel<<<edge_blocks, TPB>>>(ei, ea, 1);
    out_init_kernel<<<(NUM_GRAPHS + TPB - 1) / TPB, TPB>>>(blast, out);
    final_kernel<<<fin_blocks, TPB>>>(batch, Wlast, out);
}

// round 4
// speedup vs baseline: 1.7867x; 1.7867x over previous
#include <cuda_runtime.h>
#include <cuda_fp16.h>

#define N_NODES   50000
#define N_EDGES   800000
#define F_IN      16
#define F_EDGE    8
#define H         8
#define NUM_GRAPHS 512

// Q (o-major, fp16): Q[n][j*8+f], row = 64 halves = 128 B, line-aligned.
__device__ __align__(128) __half g_Qh[N_NODES * 64];       // 6.4 MB
__device__ __align__(16)  float  g_bias[N_NODES * H];      // 1.6 MB  (x@Be per node)
__device__ __align__(16)  float  g_agg1[N_NODES * H];      // 1.6 MB
__device__ __align__(16)  float  g_agg2[N_NODES * H];      // 1.6 MB

// ---------------------------------------------------------------------------
// Layer-1 node precompute (8 lanes per node, lane j = output channel j):
//   Qh[n][j*8+f] = sum_i x[n,i]*We1[f, i*8+j]    (fp16, o-major)
//   bias[n][j]   = sum_i x[n,i]*be1[i*8+j]
//   agg1[n][j]   = x[n]@root1[:,j] + b1[j]
// ---------------------------------------------------------------------------
__global__ void node1_kernel(const float* __restrict__ x,
                             const float* __restrict__ We1,
                             const float* __restrict__ be1,
                             const float* __restrict__ root1,
                             const float* __restrict__ b1) {
    __shared__ float sW[F_EDGE * F_IN * H];  // 1024
    __shared__ float sR[F_IN * H];           // 128
    __shared__ float sB[F_IN * H];           // 128
    __shared__ float sb[H];
    for (int i = threadIdx.x; i < F_EDGE * F_IN * H; i += blockDim.x) sW[i] = We1[i];
    for (int i = threadIdx.x; i < F_IN * H; i += blockDim.x) { sR[i] = root1[i]; sB[i] = be1[i]; }
    if (threadIdx.x < H) sb[threadIdx.x] = b1[threadIdx.x];
    __syncthreads();

    int gid = blockIdx.x * blockDim.x + threadIdx.x;
    int n = gid >> 3, j = gid & 7;
    if (n >= N_NODES) return;

    float xv[F_IN];
    const float4* xp = (const float4*)(x + n * F_IN);
    #pragma unroll
    for (int v = 0; v < 4; v++) {
        float4 t = xp[v];
        xv[v * 4 + 0] = t.x; xv[v * 4 + 1] = t.y; xv[v * 4 + 2] = t.z; xv[v * 4 + 3] = t.w;
    }

    float q[8];
    #pragma unroll
    for (int f = 0; f < 8; f++) {
        float s = 0.f;
        #pragma unroll
        for (int i = 0; i < F_IN; i++) s = fmaf(xv[i], sW[f * 128 + i * 8 + j], s);
        q[f] = s;
    }
    // pack 8 halves -> one 16B store
    union { uint4 u; __half2 h[4]; } pk;
    pk.h[0] = __floats2half2_rn(q[0], q[1]);
    pk.h[1] = __floats2half2_rn(q[2], q[3]);
    pk.h[2] = __floats2half2_rn(q[4], q[5]);
    pk.h[3] = __floats2half2_rn(q[6], q[7]);
    *(uint4*)(g_Qh + n * 64 + j * 8) = pk.u;

    float qb = 0.f, r = sb[j];
    #pragma unroll
    for (int i = 0; i < F_IN; i++) {
        qb = fmaf(xv[i], sB[i * 8 + j], qb);
        r  = fmaf(xv[i], sR[i * 8 + j], r);
    }
    g_bias[n * 8 + j] = qb;
    g_agg1[n * 8 + j] = r;
}

// ---------------------------------------------------------------------------
// Layer-2 node precompute: h = relu(agg1); same structure
// ---------------------------------------------------------------------------
__global__ void node2_kernel(const float* __restrict__ We2,
                             const float* __restrict__ be2,
                             const float* __restrict__ root2,
                             const float* __restrict__ b2) {
    __shared__ float sW[F_EDGE * H * H];  // 512
    __shared__ float sR[H * H];           // 64
    __shared__ float sB[H * H];           // 64
    __shared__ float sb[H];
    for (int i = threadIdx.x; i < F_EDGE * H * H; i += blockDim.x) sW[i] = We2[i];
    for (int i = threadIdx.x; i < H * H; i += blockDim.x) { sR[i] = root2[i]; sB[i] = be2[i]; }
    if (threadIdx.x < H) sb[threadIdx.x] = b2[threadIdx.x];
    __syncthreads();

    int gid = blockIdx.x * blockDim.x + threadIdx.x;
    int n = gid >> 3, j = gid & 7;
    if (n >= N_NODES) return;

    float h[H];
    const float4* hp = (const float4*)(g_agg1 + n * 8);
    float4 a0 = hp[0], a1 = hp[1];
    h[0] = fmaxf(a0.x, 0.f); h[1] = fmaxf(a0.y, 0.f);
    h[2] = fmaxf(a0.z, 0.f); h[3] = fmaxf(a0.w, 0.f);
    h[4] = fmaxf(a1.x, 0.f); h[5] = fmaxf(a1.y, 0.f);
    h[6] = fmaxf(a1.z, 0.f); h[7] = fmaxf(a1.w, 0.f);

    float q[8];
    #pragma unroll
    for (int f = 0; f < 8; f++) {
        float s = 0.f;
        #pragma unroll
        for (int i = 0; i < H; i++) s = fmaf(h[i], sW[f * 64 + i * 8 + j], s);
        q[f] = s;
    }
    union { uint4 u; __half2 hh[4]; } pk;
    pk.hh[0] = __floats2half2_rn(q[0], q[1]);
    pk.hh[1] = __floats2half2_rn(q[2], q[3]);
    pk.hh[2] = __floats2half2_rn(q[4], q[5]);
    pk.hh[3] = __floats2half2_rn(q[6], q[7]);
    *(uint4*)(g_Qh + n * 64 + j * 8) = pk.u;

    float qb = 0.f, r = sb[j];
    #pragma unroll
    for (int i = 0; i < H; i++) {
        qb = fmaf(h[i], sB[i * 8 + j], qb);
        r  = fmaf(h[i], sR[i * 8 + j], r);
    }
    g_bias[n * 8 + j] = qb;
    g_agg2[n * 8 + j] = r;
}

// ---------------------------------------------------------------------------
// Edge pass: 8 lanes per edge, 2 edges per thread, fp16 Q.
// Lane j: one LDG.128 covers Q[src][j*8..j*8+7] (whole group = ONE 128B line),
//         r = bias[src][j] + sum_f ea[e,f]*Q[src][j*8+f]  (fp32 accum)
//         atomicAdd(agg[dst*8+j], r)
// ---------------------------------------------------------------------------
#define EPT 2
#define HALF_E (N_EDGES / EPT)

__global__ void __launch_bounds__(256) edge_kernel(const int* __restrict__ ei,
                                                   const float* __restrict__ ea,
                                                   int layer) {
    int gid = blockIdx.x * blockDim.x + threadIdx.x;
    int e0 = gid >> 3, j = gid & 7;
    float* agg = layer ? g_agg2 : g_agg1;

    #pragma unroll
    for (int k = 0; k < EPT; k++) {
        int e = e0 + k * HALF_E;
        int s = __ldg(&ei[e]);
        int d = __ldg(&ei[N_EDGES + e]);

        const float4* eap = (const float4*)(ea + e * 8);
        float4 a0 = __ldg(eap);
        float4 a1 = __ldg(eap + 1);

        uint4 qraw = __ldg((const uint4*)(g_Qh + s * 64 + j * 8));
        union { uint4 u; __half2 h[4]; } qk; qk.u = qraw;
        float2 f0 = __half22float2(qk.h[0]);
        float2 f1 = __half22float2(qk.h[1]);
        float2 f2 = __half22float2(qk.h[2]);
        float2 f3 = __half22float2(qk.h[3]);

        float r = __ldg(&g_bias[s * 8 + j]);
        r = fmaf(a0.x, f0.x, r);
        r = fmaf(a0.y, f0.y, r);
        r = fmaf(a0.z, f1.x, r);
        r = fmaf(a0.w, f1.y, r);
        r = fmaf(a1.x, f2.x, r);
        r = fmaf(a1.y, f2.y, r);
        r = fmaf(a1.z, f3.x, r);
        r = fmaf(a1.w, f3.y, r);

        atomicAdd(&agg[d * 8 + j], r);
    }
}

// ---------------------------------------------------------------------------
// Output init + fused relu / pool / readout with warp-aggregated atomics.
// ---------------------------------------------------------------------------
__global__ void out_init_kernel(const float* __restrict__ blast, float* __restrict__ out) {
    int g = blockIdx.x * blockDim.x + threadIdx.x;
    if (g < NUM_GRAPHS) out[g] = blast[0];
}

__global__ void final_kernel(const int* __restrict__ batch,
                             const float* __restrict__ Wlast,
                             float* __restrict__ out) {
    int n = blockIdx.x * blockDim.x + threadIdx.x;
    bool valid = (n < N_NODES);
    int nc = valid ? n : (N_NODES - 1);

    const float4* ap = (const float4*)(g_agg2 + nc * 8);
    float4 a0 = ap[0], a1 = ap[1];
    float v = 0.f;
    v = fmaf(fmaxf(a0.x, 0.f), __ldg(&Wlast[0]), v);
    v = fmaf(fmaxf(a0.y, 0.f), __ldg(&Wlast[1]), v);
    v = fmaf(fmaxf(a0.z, 0.f), __ldg(&Wlast[2]), v);
    v = fmaf(fmaxf(a0.w, 0.f), __ldg(&Wlast[3]), v);
    v = fmaf(fmaxf(a1.x, 0.f), __ldg(&Wlast[4]), v);
    v = fmaf(fmaxf(a1.y, 0.f), __ldg(&Wlast[5]), v);
    v = fmaf(fmaxf(a1.z, 0.f), __ldg(&Wlast[6]), v);
    v = fmaf(fmaxf(a1.w, 0.f), __ldg(&Wlast[7]), v);
    if (!valid) v = 0.f;

    int b = __ldg(&batch[nc]);
    int b0 = __shfl_sync(0xffffffffu, b, 0);
    if (__all_sync(0xffffffffu, b == b0)) {
        #pragma unroll
        for (int off = 16; off >= 1; off >>= 1)
            v += __shfl_xor_sync(0xffffffffu, v, off, 32);
        if ((threadIdx.x & 31) == 0) atomicAdd(&out[b0], v);
    } else {
        if (valid) atomicAdd(&out[b], v);
    }
}

// ---------------------------------------------------------------------------
extern "C" void kernel_launch(void* const* d_in, const int* in_sizes, int n_in,
                              void* d_out, int out_size) {
    const float* x     = (const float*)d_in[0];
    const int*   ei    = (const int*)  d_in[1];
    const float* ea    = (const float*)d_in[2];
    const int*   batch = (const int*)  d_in[3];
    const float* We1   = (const float*)d_in[4];
    const float* be1   = (const float*)d_in[5];
    const float* root1 = (const float*)d_in[6];
    const float* b1    = (const float*)d_in[7];
    const float* We2   = (const float*)d_in[8];
    const float* be2   = (const float*)d_in[9];
    const float* root2 = (const float*)d_in[10];
    const float* b2    = (const float*)d_in[11];
    const float* Wlast = (const float*)d_in[12];
    const float* blast = (const float*)d_in[13];
    float* out = (float*)d_out;

    const int TPB = 256;
    int node_blocks = (N_NODES * 8 + TPB - 1) / TPB;
    int edge_blocks = (HALF_E * 8) / TPB;           // 12500, exact
    int fin_blocks  = (N_NODES + TPB - 1) / TPB;

    node1_kernel<<<node_blocks, TPB>>>(x, We1, be1, root1, b1);
    edge_kernel<<<edge_blocks, TPB>>>(ei, ea, 0);
    node2_kernel<<<node_blocks, TPB>>>(We2, be2, root2, b2);
    edge_kernel<<<edge_blocks, TPB>>>(ei, ea, 1);
    out_init_kernel<<<(NUM_GRAPHS + TPB - 1) / TPB, TPB>>>(blast, out);
    final_kernel<<<fin_blocks, TPB>>>(batch, Wlast, out);
}